// round 2
// baseline (speedup 1.0000x reference)
#include <cuda_runtime.h>
#include <cstdint>

#define NB 1024
#define NT 512
#define NL 64

__device__ __forceinline__ unsigned long long pack2(float a, float b) {
    unsigned long long r;
    asm("mov.b64 %0, {%1,%2};" : "=l"(r) : "f"(a), "f"(b));
    return r;
}
__device__ __forceinline__ void unpack2(unsigned long long v, float& a, float& b) {
    asm("mov.b64 {%0,%1}, %2;" : "=f"(a), "=f"(b) : "l"(v));
}
__device__ __forceinline__ void ffma2(unsigned long long& acc, unsigned long long a,
                                      unsigned long long b) {
    // packed 2x fp32 FMA (Blackwell FFMA2 — only reachable via PTX fma.rn.f32x2)
    asm("fma.rn.f32x2 %0, %1, %2, %0;" : "+l"(acc) : "l"(a), "l"(b));
}

__global__ __launch_bounds__(NL) void crf_nll_kernel(
    const float* __restrict__ feats,      // [B, T, L] fp32
    const float* __restrict__ trans,      // [L, L] fp32
    const int*   __restrict__ labels,     // [B, T] int32 OR int64 (sniffed)
    float*       __restrict__ out)        // [B] fp32
{
    __shared__ __align__(16) float wbuf[2][NL];   // ping-pong normalized alphas
    __shared__ float red[2];

    const int b    = blockIdx.x;
    const int j    = threadIdx.x;   // 0..63 : output tag row
    const int lane = j & 31;
    const int warp = j >> 5;

    // ---- E row j = exp(trans[j, :]) packed as 32 f32x2 pairs, in registers ----
    unsigned long long E2[NL / 2];
    {
        const float2* tr2 = (const float2*)(trans + j * NL);
        #pragma unroll
        for (int kk = 0; kk < NL / 2; ++kk) {
            float2 v = tr2[kk];
            E2[kk] = pack2(__expf(v.x), __expf(v.y));   // exp(-10000) -> 0 exactly
        }
    }

    // ---- init: alpha0 = NEG everywhere except START(=0) -> w = delta at 0, C = 0 ----
    wbuf[0][j] = (j == 0) ? 1.0f : 0.0f;
    __syncthreads();

    const float* fb = feats + (size_t)b * NT * NL;
    float C = 0.0f;
    float fnext = fb[NL + j];   // prefetch t=1

    #pragma unroll 1
    for (int t = 1; t < NT; ++t) {
        float f = fnext;
        if (t + 1 < NT) fnext = fb[(size_t)(t + 1) * NL + j];   // prefetch next step
        float ef = __expf(f);

        // u[j] = (sum_k E[j,k] * w[k]) * exp(f[j])   -- 32 packed FFMA2, w broadcast LDS.128
        const ulonglong2* wv = (const ulonglong2*)wbuf[(t - 1) & 1];
        unsigned long long acc0 = 0ull, acc1 = 0ull;
        #pragma unroll
        for (int q = 0; q < 16; ++q) {
            ulonglong2 wq = wv[q];
            ffma2(acc0, E2[2 * q],     wq.x);
            ffma2(acc1, E2[2 * q + 1], wq.y);
        }
        float a0, a1, b0, b1;
        unpack2(acc0, a0, a1);
        unpack2(acc1, b0, b1);
        float u = ((a0 + b0) + (a1 + b1)) * ef;

        // renormalize every 4 steps: C += log(max u), w = u / max
        float rs = 1.0f;
        if ((t & 3) == 0) {
            float m = u;
            #pragma unroll
            for (int o = 16; o; o >>= 1)
                m = fmaxf(m, __shfl_xor_sync(0xffffffffu, m, o));
            if (lane == 0) red[warp] = m;
            __syncthreads();
            float mx = fmaxf(red[0], red[1]);
            C += __logf(mx);
            rs = __frcp_rn(mx);
        }
        wbuf[t & 1][j] = u * rs;
        __syncthreads();
    }

    // ---- log_Z = C + log(sum_j w[j]) ----
    float s = wbuf[(NT - 1) & 1][j];
    #pragma unroll
    for (int o = 16; o; o >>= 1) s += __shfl_xor_sync(0xffffffffu, s, o);
    if (lane == 0) red[warp] = s;
    __syncthreads();
    float logZ = C + __logf(red[0] + red[1]);
    __syncthreads();   // before red is reused below

    // ---- gold path score ----
    // label dtype sniff: int64 little-endian => odd 32-bit words are all zero
    const int* li = labels;
    bool i64 = ((li[1] | li[3] | li[5] | li[7] | li[9] | li[11] | li[13] | li[15]) == 0);
    const long long* ll = (const long long*)labels;

    float g = 0.0f;
    for (int t = 1 + j; t < NT; t += NL) {
        int curt, prv;
        if (i64) {
            curt = (int)ll[(size_t)b * NT + t];
            prv  = (int)ll[(size_t)b * NT + t - 1];
        } else {
            curt = li[(size_t)b * NT + t];
            prv  = li[(size_t)b * NT + t - 1];
        }
        g += trans[curt * NL + prv] + fb[(size_t)t * NL + curt];
    }
    #pragma unroll
    for (int o = 16; o; o >>= 1) g += __shfl_xor_sync(0xffffffffu, g, o);
    if (lane == 0) red[warp] = g;
    __syncthreads();

    if (j == 0) out[b] = logZ - (red[0] + red[1]);
}

extern "C" void kernel_launch(void* const* d_in, const int* in_sizes, int n_in,
                              void* d_out, int out_size) {
    const float* feats  = (const float*)d_in[0];
    const float* trans  = (const float*)d_in[1];
    const int*   labels = (const int*)d_in[2];
    float*       out    = (float*)d_out;
    crf_nll_kernel<<<NB, NL>>>(feats, trans, labels, out);
}